// round 1
// baseline (speedup 1.0000x reference)
#include <cuda_runtime.h>
#include <cuda_bf16.h>
#include <math.h>

// Problem constants (fixed by the reference)
#define BB 2
#define SS 2048
#define DD 512
#define VV 32000
#define HH 4
#define DH 128
#define WW 3
#define NN (BB*SS)   // 4096

// Scratch (device globals; no allocation allowed)
__device__ float g_x   [NN*DD];
__device__ float g_x2  [NN*DD];
__device__ float g_wx  [NN*DD];
__device__ float g_agg [NN*DD];
__device__ float g_ssrc[NN*HH];
__device__ float g_sdst[NN*HH];

// ---------------------------------------------------------------------------
// Embedding gather: x[n,:] = emb[ids[n],:]
// ---------------------------------------------------------------------------
__global__ void gather_k(const int* __restrict__ ids,
                         const float* __restrict__ emb,
                         float* __restrict__ x)
{
    int idx = blockIdx.x * blockDim.x + threadIdx.x;   // over NN*DD/4
    int n  = idx / (DD/4);
    int d4 = idx % (DD/4);
    const float4* srcp = (const float4*)(emb + (size_t)ids[n]*DD) + d4;
    float4* dstp = (float4*)(x + (size_t)n*DD) + d4;
    *dstp = *srcp;
}

// ---------------------------------------------------------------------------
// Generic NT GEMM: C[M,Ncol] = A[M,K] @ B[Ncol,K]^T (+bias)(+activation)
// EPI: 0 = none, 1 = bias + ELU, 2 = bias only
// Dims assumed divisible by tile sizes (true for this problem).
// ---------------------------------------------------------------------------
template<int BM,int BN,int BK,int TM,int TN,int EPI>
__global__ void gemm_nt(const float* __restrict__ A,
                        const float* __restrict__ B,
                        const float* __restrict__ bias,
                        float* __restrict__ C,
                        int M, int Ncol, int K)
{
    constexpr int PAD = 4;
    __shared__ float As[BK][BM+PAD];
    __shared__ float Bs[BK][BN+PAD];

    const int tid = threadIdx.x;              // (BM/TM)*(BN/TN) threads
    constexpr int NTX = BN / TN;
    const int tx = tid % NTX;
    const int ty = tid / NTX;
    const int row0 = blockIdx.y * BM;
    const int col0 = blockIdx.x * BN;

    float acc[TM][TN];
    #pragma unroll
    for (int i = 0; i < TM; i++)
        #pragma unroll
        for (int j = 0; j < TN; j++) acc[i][j] = 0.f;

    for (int k0 = 0; k0 < K; k0 += BK) {
        // load A tile (transposed into smem)
        #pragma unroll
        for (int t = tid; t < BM*BK/4; t += (BM/TM)*(BN/TN)) {
            int r = t / (BK/4);
            int c = (t % (BK/4)) * 4;
            float4 v = *(const float4*)(A + (size_t)(row0 + r)*K + k0 + c);
            As[c+0][r] = v.x; As[c+1][r] = v.y; As[c+2][r] = v.z; As[c+3][r] = v.w;
        }
        // load B tile (transposed into smem)
        #pragma unroll
        for (int t = tid; t < BN*BK/4; t += (BM/TM)*(BN/TN)) {
            int r = t / (BK/4);
            int c = (t % (BK/4)) * 4;
            float4 v = *(const float4*)(B + (size_t)(col0 + r)*K + k0 + c);
            Bs[c+0][r] = v.x; Bs[c+1][r] = v.y; Bs[c+2][r] = v.z; Bs[c+3][r] = v.w;
        }
        __syncthreads();

        #pragma unroll
        for (int k = 0; k < BK; k++) {
            float af[TM], bf[TN];
            #pragma unroll
            for (int i = 0; i < TM; i += 4)
                *(float4*)&af[i] = *(const float4*)&As[k][ty*TM + i];
            #pragma unroll
            for (int j = 0; j < TN; j += 4)
                *(float4*)&bf[j] = *(const float4*)&Bs[k][tx*TN + j];
            #pragma unroll
            for (int i = 0; i < TM; i++)
                #pragma unroll
                for (int j = 0; j < TN; j++)
                    acc[i][j] = fmaf(af[i], bf[j], acc[i][j]);
        }
        __syncthreads();
    }

    // epilogue
    #pragma unroll
    for (int i = 0; i < TM; i++) {
        int row = row0 + ty*TM + i;
        #pragma unroll
        for (int j = 0; j < TN; j += 4) {
            int col = col0 + tx*TN + j;
            float4 v;
            v.x = acc[i][j+0]; v.y = acc[i][j+1]; v.z = acc[i][j+2]; v.w = acc[i][j+3];
            if (EPI >= 1) {
                v.x += bias[col+0]; v.y += bias[col+1];
                v.z += bias[col+2]; v.w += bias[col+3];
            }
            if (EPI == 1) {  // ELU
                v.x = v.x > 0.f ? v.x : (expf(v.x) - 1.f);
                v.y = v.y > 0.f ? v.y : (expf(v.y) - 1.f);
                v.z = v.z > 0.f ? v.z : (expf(v.z) - 1.f);
                v.w = v.w > 0.f ? v.w : (expf(v.w) - 1.f);
            }
            *(float4*)(C + (size_t)row*Ncol + col) = v;
        }
    }
}

// ---------------------------------------------------------------------------
// Per-node attention scores: s_src[n,h] = <Wx[n,h,:], a[h,0:DH]>,
//                            s_dst[n,h] = <Wx[n,h,:], a[h,DH:2DH]>
// One warp per (n,h).
// ---------------------------------------------------------------------------
__global__ void scores_k(const float* __restrict__ wx,
                         const float* __restrict__ a,
                         float* __restrict__ ssrc,
                         float* __restrict__ sdst)
{
    int w    = (blockIdx.x * blockDim.x + threadIdx.x) >> 5;
    int lane = threadIdx.x & 31;
    if (w >= NN*HH) return;
    int n = w / HH, h = w % HH;
    const float* row = wx + (size_t)n*DD + h*DH;
    const float* au  = a + (size_t)h*2*DH;
    const float* av  = au + DH;

    int d = lane * 4;   // DH=128 -> exactly one float4 per lane
    float4 x = *(const float4*)(row + d);
    float4 u = *(const float4*)(au  + d);
    float4 v = *(const float4*)(av  + d);
    float s1 = x.x*u.x + x.y*u.y + x.z*u.z + x.w*u.w;
    float s2 = x.x*v.x + x.y*v.y + x.z*v.z + x.w*v.w;
    #pragma unroll
    for (int o = 16; o; o >>= 1) {
        s1 += __shfl_xor_sync(0xffffffffu, s1, o);
        s2 += __shfl_xor_sync(0xffffffffu, s2, o);
    }
    if (lane == 0) { ssrc[w] = s1; sdst[w] = s2; }
}

// ---------------------------------------------------------------------------
// Windowed GAT aggregation. Edges are token i -> j in [i-W, i+W], j != i,
// within the same sequence. Segment softmax over incoming edges of each dst
// node n, then agg[n,h,:] = sum_j alpha_j * Wx[j,h,:].
// One block per node (128 threads = 4 warps, warp h handles head h).
// ---------------------------------------------------------------------------
__global__ void attn_k(const float* __restrict__ wx,
                       const float* __restrict__ ssrc,
                       const float* __restrict__ sdst,
                       float* __restrict__ agg)
{
    int n    = blockIdx.x;
    int h    = threadIdx.x >> 5;
    int lane = threadIdx.x & 31;
    int i    = n % SS;   // position within sequence

    float sd = sdst[(size_t)n*HH + h];

    float e[2*WW];
    int   jn[2*WW];
    int cnt = 0;
    #pragma unroll
    for (int off = -WW; off <= WW; off++) {
        if (off == 0) continue;
        int ji = i + off;
        if (ji < 0 || ji >= SS) continue;
        int j = n + off;
        float v = ssrc[(size_t)j*HH + h] + sd;
        v = v >= 0.f ? v : 0.2f * v;   // LeakyReLU(0.2)
        e[cnt] = v; jn[cnt] = j; cnt++;
    }
    float m = -1e30f;
    for (int c = 0; c < cnt; c++) m = fmaxf(m, e[c]);
    float den = 0.f;
    for (int c = 0; c < cnt; c++) { e[c] = expf(e[c] - m); den += e[c]; }
    float inv = 1.f / (den + 1e-16f);

    int d = lane * 4;  // DH=128 -> one float4 per lane
    float4 accv = make_float4(0.f, 0.f, 0.f, 0.f);
    for (int c = 0; c < cnt; c++) {
        const float4 xv = *(const float4*)(wx + (size_t)jn[c]*DD + h*DH + d);
        float al = e[c] * inv;
        accv.x = fmaf(al, xv.x, accv.x);
        accv.y = fmaf(al, xv.y, accv.y);
        accv.z = fmaf(al, xv.z, accv.z);
        accv.w = fmaf(al, xv.w, accv.w);
    }
    *(float4*)(agg + (size_t)n*DD + h*DH + d) = accv;
}

// ---------------------------------------------------------------------------
// Host side
// ---------------------------------------------------------------------------
static void run_gat_layer(const float* xin, const float* Wl, const float* a,
                          const float* ow, const float* ob, float* xout,
                          float* wx, float* ssrc, float* sdst, float* agg)
{
    dim3 gsmall(DD/64, NN/64);
    gemm_nt<64,64,8,4,4,0><<<gsmall, 256>>>(xin, Wl, nullptr, wx, NN, DD, DD);
    scores_k<<<(NN*HH*32)/256, 256>>>(wx, a, ssrc, sdst);
    attn_k<<<NN, 128>>>(wx, ssrc, sdst, agg);
    gemm_nt<64,64,8,4,4,1><<<gsmall, 256>>>(agg, ow, ob, xout, NN, DD, DD);
}

extern "C" void kernel_launch(void* const* d_in, const int* in_sizes, int n_in,
                              void* d_out, int out_size)
{
    const int*   ids = (const int*)  d_in[0];
    const float* emb = (const float*)d_in[1];
    const float* W1  = (const float*)d_in[2];
    const float* a1  = (const float*)d_in[3];
    const float* o1w = (const float*)d_in[4];
    const float* o1b = (const float*)d_in[5];
    const float* W2  = (const float*)d_in[6];
    const float* a2  = (const float*)d_in[7];
    const float* o2w = (const float*)d_in[8];
    const float* o2b = (const float*)d_in[9];
    const float* lmw = (const float*)d_in[10];
    const float* lmb = (const float*)d_in[11];
    // d_in[12]=src, d_in[13]=dst: unused (window structure exploited directly)
    float* out = (float*)d_out;

    float *px, *px2, *pwx, *pagg, *pssrc, *psdst;
    cudaGetSymbolAddress((void**)&px,    g_x);
    cudaGetSymbolAddress((void**)&px2,   g_x2);
    cudaGetSymbolAddress((void**)&pwx,   g_wx);
    cudaGetSymbolAddress((void**)&pagg,  g_agg);
    cudaGetSymbolAddress((void**)&pssrc, g_ssrc);
    cudaGetSymbolAddress((void**)&psdst, g_sdst);

    gather_k<<<(NN*DD/4)/256, 256>>>(ids, emb, px);

    run_gat_layer(px,  W1, a1, o1w, o1b, px2, pwx, pssrc, psdst, pagg);
    run_gat_layer(px2, W2, a2, o2w, o2b, px,  pwx, pssrc, psdst, pagg);

    dim3 gbig(VV/128, NN/128);
    gemm_nt<128,128,8,8,8,2><<<gbig, 256>>>(px, lmw, lmb, out, NN, VV, DD);
}

// round 3
// speedup vs baseline: 2.5747x; 2.5747x over previous
#include <cuda_runtime.h>
#include <cuda_bf16.h>
#include <math.h>
#include <stdint.h>

// Problem constants (fixed by the reference)
#define BB 2
#define SS 2048
#define DD 512
#define VV 32000
#define HH 4
#define DH 128
#define WW 3
#define NN (BB*SS)   // 4096
#define KP 1536      // split-bf16 K' = 3*512
#define NCHUNK 24    // KP / 64

// Scratch (device globals; no allocation allowed)
__device__ float g_x   [NN*DD];
__device__ float g_x2  [NN*DD];
__device__ float g_wx  [NN*DD];
__device__ float g_agg [NN*DD];
__device__ float g_ssrc[NN*HH];
__device__ float g_sdst[NN*HH];
__device__ __nv_bfloat16 g_Ap[(size_t)NN*KP];   // [Ah | Ah | Al]
__device__ __nv_bfloat16 g_Bp[(size_t)VV*KP];   // [Bh | Bl | Bh]

// ---------------------------------------------------------------------------
// PTX helpers (sm_80-era only: cp.async, ldmatrix, mma.sync — all valid at
// virtual target compute_103; tcgen05 is NOT, the harness PTX target rejects it)
// ---------------------------------------------------------------------------
__device__ __forceinline__ uint32_t smem_u32(const void* p) {
    uint32_t a;
    asm("{ .reg .u64 t; cvta.to.shared.u64 t, %1; cvt.u32.u64 %0, t; }"
        : "=r"(a) : "l"(p));
    return a;
}
__device__ __forceinline__ void cp_async16(uint32_t dst, const void* src) {
    asm volatile("cp.async.cg.shared.global [%0], [%1], 16;\n" :: "r"(dst), "l"(src));
}
#define CP_COMMIT() asm volatile("cp.async.commit_group;\n" ::: "memory")
template<int Nw> __device__ __forceinline__ void cp_wait() {
    asm volatile("cp.async.wait_group %0;\n" :: "n"(Nw) : "memory");
}
__device__ __forceinline__ void ldmatrix_x4(uint32_t& r0, uint32_t& r1,
                                            uint32_t& r2, uint32_t& r3, uint32_t addr) {
    asm volatile("ldmatrix.sync.aligned.m8n8.x4.shared.b16 {%0,%1,%2,%3}, [%4];\n"
                 : "=r"(r0), "=r"(r1), "=r"(r2), "=r"(r3) : "r"(addr));
}
__device__ __forceinline__ void mma_bf16(float& c0, float& c1, float& c2, float& c3,
                                         uint32_t a0, uint32_t a1, uint32_t a2, uint32_t a3,
                                         uint32_t b0, uint32_t b1) {
    asm volatile(
        "mma.sync.aligned.m16n8k16.row.col.f32.bf16.bf16.f32 "
        "{%0,%1,%2,%3}, {%4,%5,%6,%7}, {%8,%9}, {%0,%1,%2,%3};\n"
        : "+f"(c0), "+f"(c1), "+f"(c2), "+f"(c3)
        : "r"(a0), "r"(a1), "r"(a2), "r"(a3), "r"(b0), "r"(b1));
}

// ---------------------------------------------------------------------------
// Embedding gather
// ---------------------------------------------------------------------------
__global__ void gather_k(const int* __restrict__ ids,
                         const float* __restrict__ emb,
                         float* __restrict__ x)
{
    int idx = blockIdx.x * blockDim.x + threadIdx.x;
    int n  = idx / (DD/4);
    int d4 = idx % (DD/4);
    const float4* srcp = (const float4*)(emb + (size_t)ids[n]*DD) + d4;
    float4* dstp = (float4*)(x + (size_t)n*DD) + d4;
    *dstp = *srcp;
}

// ---------------------------------------------------------------------------
// fp32 -> split bf16 conversions (K-concatenated layouts)
// A' blocks: (hi, hi, lo).  B' blocks: (hi, lo, hi).
// C = Ah*Bh + Ah*Bl + Al*Bh  (missing Al*Bl term is ~2^-18 relative)
// ---------------------------------------------------------------------------
__global__ void conv_A_k(const float* __restrict__ src, __nv_bfloat16* __restrict__ dst)
{
    size_t i = (size_t)blockIdx.x * blockDim.x + threadIdx.x;
    size_t r = i / (DD/4);
    int c = (int)(i % (DD/4)) * 4;
    float4 v = *(const float4*)(src + r*DD + c);
    float f[4] = {v.x, v.y, v.z, v.w};
    __nv_bfloat16* base = dst + r*KP + c;
    #pragma unroll
    for (int j = 0; j < 4; j++) {
        __nv_bfloat16 h = __float2bfloat16(f[j]);
        __nv_bfloat16 l = __float2bfloat16(f[j] - __bfloat162float(h));
        base[j]        = h;   // block 0: hi
        base[512 + j]  = h;   // block 1: hi
        base[1024 + j] = l;   // block 2: lo
    }
}
__global__ void conv_B_k(const float* __restrict__ src, __nv_bfloat16* __restrict__ dst)
{
    size_t i = (size_t)blockIdx.x * blockDim.x + threadIdx.x;
    size_t r = i / (DD/4);
    int c = (int)(i % (DD/4)) * 4;
    float4 v = *(const float4*)(src + r*DD + c);
    float f[4] = {v.x, v.y, v.z, v.w};
    __nv_bfloat16* base = dst + r*KP + c;
    #pragma unroll
    for (int j = 0; j < 4; j++) {
        __nv_bfloat16 h = __float2bfloat16(f[j]);
        __nv_bfloat16 l = __float2bfloat16(f[j] - __bfloat162float(h));
        base[j]        = h;   // block 0: hi
        base[512 + j]  = l;   // block 1: lo
        base[1024 + j] = h;   // block 2: hi
    }
}

// ---------------------------------------------------------------------------
// fp32 NT GEMM for the small GAT projections
// ---------------------------------------------------------------------------
template<int BM,int BN,int BK,int TM,int TN,int EPI>
__global__ void gemm_nt(const float* __restrict__ A,
                        const float* __restrict__ B,
                        const float* __restrict__ bias,
                        float* __restrict__ C,
                        int M, int Ncol, int K)
{
    constexpr int PAD = 4;
    __shared__ float As[BK][BM+PAD];
    __shared__ float Bs[BK][BN+PAD];

    const int tid = threadIdx.x;
    constexpr int NTX = BN / TN;
    const int tx = tid % NTX;
    const int ty = tid / NTX;
    const int row0 = blockIdx.y * BM;
    const int col0 = blockIdx.x * BN;

    float acc[TM][TN];
    #pragma unroll
    for (int i = 0; i < TM; i++)
        #pragma unroll
        for (int j = 0; j < TN; j++) acc[i][j] = 0.f;

    for (int k0 = 0; k0 < K; k0 += BK) {
        #pragma unroll
        for (int t = tid; t < BM*BK/4; t += (BM/TM)*(BN/TN)) {
            int r = t / (BK/4);
            int c = (t % (BK/4)) * 4;
            float4 v = *(const float4*)(A + (size_t)(row0 + r)*K + k0 + c);
            As[c+0][r] = v.x; As[c+1][r] = v.y; As[c+2][r] = v.z; As[c+3][r] = v.w;
        }
        #pragma unroll
        for (int t = tid; t < BN*BK/4; t += (BM/TM)*(BN/TN)) {
            int r = t / (BK/4);
            int c = (t % (BK/4)) * 4;
            float4 v = *(const float4*)(B + (size_t)(col0 + r)*K + k0 + c);
            Bs[c+0][r] = v.x; Bs[c+1][r] = v.y; Bs[c+2][r] = v.z; Bs[c+3][r] = v.w;
        }
        __syncthreads();

        #pragma unroll
        for (int k = 0; k < BK; k++) {
            float af[TM], bf[TN];
            #pragma unroll
            for (int i = 0; i < TM; i += 4)
                *(float4*)&af[i] = *(const float4*)&As[k][ty*TM + i];
            #pragma unroll
            for (int j = 0; j < TN; j += 4)
                *(float4*)&bf[j] = *(const float4*)&Bs[k][tx*TN + j];
            #pragma unroll
            for (int i = 0; i < TM; i++)
                #pragma unroll
                for (int j = 0; j < TN; j++)
                    acc[i][j] = fmaf(af[i], bf[j], acc[i][j]);
        }
        __syncthreads();
    }

    #pragma unroll
    for (int i = 0; i < TM; i++) {
        int row = row0 + ty*TM + i;
        #pragma unroll
        for (int j = 0; j < TN; j += 4) {
            int col = col0 + tx*TN + j;
            float4 v;
            v.x = acc[i][j+0]; v.y = acc[i][j+1]; v.z = acc[i][j+2]; v.w = acc[i][j+3];
            if (EPI >= 1) {
                v.x += bias[col+0]; v.y += bias[col+1];
                v.z += bias[col+2]; v.w += bias[col+3];
            }
            if (EPI == 1) {
                v.x = v.x > 0.f ? v.x : (expf(v.x) - 1.f);
                v.y = v.y > 0.f ? v.y : (expf(v.y) - 1.f);
                v.z = v.z > 0.f ? v.z : (expf(v.z) - 1.f);
                v.w = v.w > 0.f ? v.w : (expf(v.w) - 1.f);
            }
            *(float4*)(C + (size_t)row*Ncol + col) = v;
        }
    }
}

// ---------------------------------------------------------------------------
// Per-node attention scores
// ---------------------------------------------------------------------------
__global__ void scores_k(const float* __restrict__ wx,
                         const float* __restrict__ a,
                         float* __restrict__ ssrc,
                         float* __restrict__ sdst)
{
    int w    = (blockIdx.x * blockDim.x + threadIdx.x) >> 5;
    int lane = threadIdx.x & 31;
    if (w >= NN*HH) return;
    int n = w / HH, h = w % HH;
    const float* row = wx + (size_t)n*DD + h*DH;
    const float* au  = a + (size_t)h*2*DH;
    const float* av  = au + DH;

    int d = lane * 4;
    float4 x = *(const float4*)(row + d);
    float4 u = *(const float4*)(au  + d);
    float4 v = *(const float4*)(av  + d);
    float s1 = x.x*u.x + x.y*u.y + x.z*u.z + x.w*u.w;
    float s2 = x.x*v.x + x.y*v.y + x.z*v.z + x.w*v.w;
    #pragma unroll
    for (int o = 16; o; o >>= 1) {
        s1 += __shfl_xor_sync(0xffffffffu, s1, o);
        s2 += __shfl_xor_sync(0xffffffffu, s2, o);
    }
    if (lane == 0) { ssrc[w] = s1; sdst[w] = s2; }
}

// ---------------------------------------------------------------------------
// Windowed GAT aggregation
// ---------------------------------------------------------------------------
__global__ void attn_k(const float* __restrict__ wx,
                       const float* __restrict__ ssrc,
                       const float* __restrict__ sdst,
                       float* __restrict__ agg)
{
    int n    = blockIdx.x;
    int h    = threadIdx.x >> 5;
    int lane = threadIdx.x & 31;
    int i    = n % SS;

    float sd = sdst[(size_t)n*HH + h];

    float e[2*WW];
    int   jn[2*WW];
    int cnt = 0;
    #pragma unroll
    for (int off = -WW; off <= WW; off++) {
        if (off == 0) continue;
        int ji = i + off;
        if (ji < 0 || ji >= SS) continue;
        int j = n + off;
        float v = ssrc[(size_t)j*HH + h] + sd;
        v = v >= 0.f ? v : 0.2f * v;
        e[cnt] = v; jn[cnt] = j; cnt++;
    }
    float m = -1e30f;
    for (int c = 0; c < cnt; c++) m = fmaxf(m, e[c]);
    float den = 0.f;
    for (int c = 0; c < cnt; c++) { e[c] = expf(e[c] - m); den += e[c]; }
    float inv = 1.f / (den + 1e-16f);

    int d = lane * 4;
    float4 accv = make_float4(0.f, 0.f, 0.f, 0.f);
    for (int c = 0; c < cnt; c++) {
        const float4 xv = *(const float4*)(wx + (size_t)jn[c]*DD + h*DH + d);
        float al = e[c] * inv;
        accv.x = fmaf(al, xv.x, accv.x);
        accv.y = fmaf(al, xv.y, accv.y);
        accv.z = fmaf(al, xv.z, accv.z);
        accv.w = fmaf(al, xv.w, accv.w);
    }
    *(float4*)(agg + (size_t)n*DD + h*DH + d) = accv;
}

// ---------------------------------------------------------------------------
// LM head: mma.sync bf16 GEMM
// C[4096,32000] = Ap[4096,1536] @ Bp[32000,1536]^T + bias
// CTA tile 128x128, BK=64, 3-stage cp.async pipeline, SW128-swizzled smem.
// 8 warps as 4(m) x 2(n); warp tile 32x64.
// ---------------------------------------------------------------------------
#define STAGES      3
#define STAGE_BYTES 32768            // A 16KB + B 16KB
#define SMEM_BYTES  (STAGES*STAGE_BYTES)

// load one 64-wide K chunk of A(128 rows) + B(128 rows) into a stage
__device__ __forceinline__ void load_stage(
    const __nv_bfloat16* __restrict__ Ap, const __nv_bfloat16* __restrict__ Bp,
    int row0, int col0, int k0, uint32_t stage_base, int tid)
{
    #pragma unroll
    for (int it = 0; it < 8; it++) {
        int g = tid + it*256;            // 0..2047
        bool isA = (g < 1024);
        int gg  = isA ? g : (g - 1024);
        int row = gg >> 3;               // 0..127
        int gran = gg & 7;               // 16B granule within 128B row
        const __nv_bfloat16* src = isA
            ? (Ap + (size_t)(row0 + row)*KP + k0 + gran*8)
            : (Bp + (size_t)(col0 + row)*KP + k0 + gran*8);
        uint32_t dst = stage_base + (isA ? 0u : 16384u)
                     + (uint32_t)row*128u + (uint32_t)((gran ^ (row & 7)) << 4);
        cp_async16(dst, src);
    }
}

__global__ void __launch_bounds__(256, 2)
lmhead_k(const __nv_bfloat16* __restrict__ Ap,
         const __nv_bfloat16* __restrict__ Bp,
         const float* __restrict__ bias,
         float* __restrict__ C)
{
    extern __shared__ char smem[];
    const uint32_t sb = smem_u32(smem);
    const int tid  = threadIdx.x;
    const int wid  = tid >> 5;
    const int lane = tid & 31;
    const int row0 = blockIdx.x * 128;
    const int col0 = blockIdx.y * 128;

    const int warp_m = wid & 3;          // 0..3 -> m offset 32*warp_m
    const int warp_n = wid >> 2;         // 0..1 -> n offset 64*warp_n

    float acc[2][8][4];
    #pragma unroll
    for (int i = 0; i < 2; i++)
        #pragma unroll
        for (int j = 0; j < 8; j++)
            #pragma unroll
            for (int q = 0; q < 4; q++) acc[i][j][q] = 0.f;

    // prologue: stages 0,1 <- chunks 0,1
    load_stage(Ap, Bp, row0, col0, 0,  sb,               tid); CP_COMMIT();
    load_stage(Ap, Bp, row0, col0, 64, sb + STAGE_BYTES, tid); CP_COMMIT();

    // per-lane ldmatrix row indices (within tile)
    const int a_row = warp_m*32 + (lane & 15);          // + mi*16
    const int a_gsel = lane >> 4;                        // k-half from lane
    const int b_row = warp_n*64 + ((lane >> 4) << 3) + (lane & 7);  // + ng*16
    const int b_gsel = (lane >> 3) & 1;

    for (int c = 0; c < NCHUNK; c++) {
        cp_wait<STAGES-2>();
        __syncthreads();   // stage c%3 visible to all; chunk c-1 compute done by all

        // prefetch chunk c+2 into stage (c+2)%3 (empty commit keeps group count uniform)
        if (c + 2 < NCHUNK)
            load_stage(Ap, Bp, row0, col0, (c+2)*64,
                       sb + ((c+2)%STAGES)*STAGE_BYTES, tid);
        CP_COMMIT();

        const uint32_t sA = sb + (c%STAGES)*STAGE_BYTES;
        const uint32_t sB = sA + 16384u;

        #pragma unroll
        for (int s = 0; s < 4; s++) {   // four k16 steps in the 64-chunk
            // A fragments: 2 x (m16 x k16)
            uint32_t a[2][4];
            #pragma unroll
            for (int mi = 0; mi < 2; mi++) {
                int r = a_row + mi*16;
                int gran = 2*s + a_gsel;
                uint32_t addr = sA + (uint32_t)r*128u + (uint32_t)((gran ^ (r & 7)) << 4);
                ldmatrix_x4(a[mi][0], a[mi][1], a[mi][2], a[mi][3], addr);
            }
            // B fragments: 4 x (n16 x k16) -> 8 n8 frags
            uint32_t b[8][2];
            #pragma unroll
            for (int ng = 0; ng < 4; ng++) {
                int r = b_row + ng*16;
                int gran = 2*s + b_gsel;
                uint32_t addr = sB + (uint32_t)r*128u + (uint32_t)((gran ^ (r & 7)) << 4);
                uint32_t r0, r1, r2, r3;
                ldmatrix_x4(r0, r1, r2, r3, addr);
                b[ng*2+0][0] = r0; b[ng*2+0][1] = r1;   // n8 j=0: k0-7, k8-15
                b[ng*2+1][0] = r2; b[ng*2+1][1] = r3;   // n8 j=1
            }
            #pragma unroll
            for (int mi = 0; mi < 2; mi++)
                #pragma unroll
                for (int nj = 0; nj < 8; nj++)
                    mma_bf16(acc[mi][nj][0], acc[mi][nj][1], acc[mi][nj][2], acc[mi][nj][3],
                             a[mi][0], a[mi][1], a[mi][2], a[mi][3],
                             b[nj][0], b[nj][1]);
        }
        __syncthreads();   // all warps done with stage c%3 before it is refilled
    }

    // epilogue: c-frag thread map: c0,c1 -> (m = t/4, n = 2*(t%4)); c2,c3 -> m+8
    const int trow = lane >> 2;
    const int tcol = (lane & 3) * 2;
    #pragma unroll
    for (int mi = 0; mi < 2; mi++) {
        const int mbase = row0 + warp_m*32 + mi*16 + trow;
        #pragma unroll
        for (int nj = 0; nj < 8; nj++) {
            const int col = col0 + warp_n*64 + nj*8 + tcol;
            const float b0 = __ldg(bias + col);
            const float b1 = __ldg(bias + col + 1);
            float2 v0 = make_float2(acc[mi][nj][0] + b0, acc[mi][nj][1] + b1);
            float2 v1 = make_float2(acc[mi][nj][2] + b0, acc[mi][nj][3] + b1);
            *(float2*)(C + (size_t)mbase*VV + col)       = v0;
            *(float2*)(C + (size_t)(mbase+8)*VV + col)   = v1;
        }
    }
}

// ---------------------------------------------------------------------------
// Host side
// ---------------------------------------------------------------------------
static void run_gat_layer(const float* xin, const float* Wl, const float* a,
                          const float* ow, const float* ob, float* xout,
                          float* wx, float* ssrc, float* sdst, float* agg)
{
    dim3 gsmall(DD/64, NN/64);
    gemm_nt<64,64,8,4,4,0><<<gsmall, 256>>>(xin, Wl, nullptr, wx, NN, DD, DD);
    scores_k<<<(NN*HH*32)/256, 256>>>(wx, a, ssrc, sdst);
    attn_k<<<NN, 128>>>(wx, ssrc, sdst, agg);
    gemm_nt<64,64,8,4,4,1><<<gsmall, 256>>>(agg, ow, ob, xout, NN, DD, DD);
}

extern "C" void kernel_launch(void* const* d_in, const int* in_sizes, int n_in,
                              void* d_out, int out_size)
{
    const int*   ids = (const int*)  d_in[0];
    const float* emb = (const float*)d_in[1];
    const float* W1  = (const float*)d_in[2];
    const float* a1  = (const float*)d_in[3];
    const float* o1w = (const float*)d_in[4];
    const float* o1b = (const float*)d_in[5];
    const float* W2  = (const float*)d_in[6];
    const float* a2  = (const float*)d_in[7];
    const float* o2w = (const float*)d_in[8];
    const float* o2b = (const float*)d_in[9];
    const float* lmw = (const float*)d_in[10];
    const float* lmb = (const float*)d_in[11];
    float* out = (float*)d_out;

    float *px, *px2, *pwx, *pagg, *pssrc, *psdst;
    __nv_bfloat16 *pAp, *pBp;
    cudaGetSymbolAddress((void**)&px,    g_x);
    cudaGetSymbolAddress((void**)&px2,   g_x2);
    cudaGetSymbolAddress((void**)&pwx,   g_wx);
    cudaGetSymbolAddress((void**)&pagg,  g_agg);
    cudaGetSymbolAddress((void**)&pssrc, g_ssrc);
    cudaGetSymbolAddress((void**)&psdst, g_sdst);
    cudaGetSymbolAddress((void**)&pAp,   g_Ap);
    cudaGetSymbolAddress((void**)&pBp,   g_Bp);

    static bool attr_set = false;
    if (!attr_set) {
        cudaFuncSetAttribute(lmhead_k, cudaFuncAttributeMaxDynamicSharedMemorySize, SMEM_BYTES);
        attr_set = true;
    }

    // LM-head weight split (deterministic, every call)
    conv_B_k<<<(VV*(DD/4))/256, 256>>>(lmw, pBp);

    gather_k<<<(NN*DD/4)/256, 256>>>(ids, emb, px);

    run_gat_layer(px,  W1, a1, o1w, o1b, px2, pwx, pssrc, psdst, pagg);
    run_gat_layer(px2, W2, a2, o2w, o2b, px,  pwx, pssrc, psdst, pagg);

    // activation split
    conv_A_k<<<(NN*(DD/4))/256, 256>>>(px, pAp);

    // LM head: grid.x = M blocks (fast-varying -> B-tile L2 reuse)
    dim3 g(NN/128, VV/128);
    lmhead_k<<<g, 256, SMEM_BYTES>>>(pAp, pBp, lmb, out);
}